// round 3
// baseline (speedup 1.0000x reference)
#include <cuda_runtime.h>
#include <cuda_bf16.h>

// Problem constants
#define BATCH 2
#define SEQ   2048
#define DMODEL 1024
#define NHEAD 16
#define DHEAD 64

typedef unsigned long long u64;

// ---- packed f32x2 helpers (B300 FFMA2 path; ptxas only emits via PTX) ----
__device__ __forceinline__ u64 ffma2(u64 a, u64 b, u64 c) {
    u64 d;
    asm("fma.rn.f32x2 %0, %1, %2, %3;" : "=l"(d) : "l"(a), "l"(b), "l"(c));
    return d;
}
__device__ __forceinline__ u64 fmul2(u64 a, u64 b) {
    u64 d;
    asm("mul.rn.f32x2 %0, %1, %2;" : "=l"(d) : "l"(a), "l"(b));
    return d;
}
__device__ __forceinline__ u64 pack2(float x) {
    u64 d;
    asm("mov.b64 %0, {%1, %1};" : "=l"(d) : "f"(x));
    return d;
}
__device__ __forceinline__ float2 unpk2(u64 v) {
    float2 r;
    asm("mov.b64 {%0, %1}, %2;" : "=f"(r.x), "=f"(r.y) : "l"(v));
    return r;
}
__device__ __forceinline__ float hsum2(u64 v) {
    float2 r = unpk2(v);
    return r.x + r.y;
}

// ---------------------------------------------------------------------------
// Scratch for q,k,v in (b,h,s,d) layout: [B*H][S][DHEAD]
// ---------------------------------------------------------------------------
__device__ float g_q[BATCH * NHEAD * SEQ * DHEAD];
__device__ float g_k[BATCH * NHEAD * SEQ * DHEAD];
__device__ float g_v[BATCH * NHEAD * SEQ * DHEAD];

// ---------------------------------------------------------------------------
// QKV projection: Y = x @ W + b. M=4096, N=K=1024. 128x128x16 tiles, 256 thr,
// 2 CTAs/SM. FFMA2: acc pairs over adjacent n-columns, A broadcast-packed.
// ---------------------------------------------------------------------------
#define GM 128
#define GN 128
#define GK 16

__global__ __launch_bounds__(256, 2) void qkv_gemm_kernel(
    const float* __restrict__ x,
    const float* __restrict__ W0, const float* __restrict__ b0,
    const float* __restrict__ W1, const float* __restrict__ b1,
    const float* __restrict__ W2, const float* __restrict__ b2)
{
    __shared__ float As[GK][GM];
    __shared__ float Bs[GK][GN];

    const int z = blockIdx.z;
    const float* W    = (z == 0) ? W0 : (z == 1) ? W1 : W2;
    const float* bias = (z == 0) ? b0 : (z == 1) ? b1 : b2;
    float* outp       = (z == 0) ? g_q : (z == 1) ? g_k : g_v;

    const int m0 = blockIdx.y * GM;
    const int n0 = blockIdx.x * GN;
    const int tid = threadIdx.x;
    const int tx = tid & 15;
    const int ty = tid >> 4;

    u64 acc2[8][4];
    #pragma unroll
    for (int i = 0; i < 8; i++)
        #pragma unroll
        for (int jp = 0; jp < 4; jp++) acc2[i][jp] = 0ull;

    for (int kt = 0; kt < DMODEL; kt += GK) {
        #pragma unroll
        for (int u = 0; u < 2; u++) {
            int f = tid + u * 256;
            int row = f >> 2;
            int kc  = (f & 3) * 4;
            float4 a = *(const float4*)&x[(size_t)(m0 + row) * DMODEL + kt + kc];
            As[kc + 0][row] = a.x;
            As[kc + 1][row] = a.y;
            As[kc + 2][row] = a.z;
            As[kc + 3][row] = a.w;
        }
        #pragma unroll
        for (int u = 0; u < 2; u++) {
            int f = tid + u * 256;
            int kr = f >> 5;
            int nc = (f & 31) * 4;
            *(float4*)&Bs[kr][nc] =
                *(const float4*)&W[(size_t)(kt + kr) * DMODEL + n0 + nc];
        }
        __syncthreads();

        #pragma unroll
        for (int kk = 0; kk < GK; kk++) {
            float a[8];
            *(float4*)&a[0] = *(float4*)&As[kk][ty * 8];
            *(float4*)&a[4] = *(float4*)&As[kk][ty * 8 + 4];
            ulonglong2 b01 = *(ulonglong2*)&Bs[kk][tx * 8];
            ulonglong2 b23 = *(ulonglong2*)&Bs[kk][tx * 8 + 4];
            u64 bb[4] = {b01.x, b01.y, b23.x, b23.y};
            #pragma unroll
            for (int i = 0; i < 8; i++) {
                u64 ai = pack2(a[i]);
                #pragma unroll
                for (int jp = 0; jp < 4; jp++)
                    acc2[i][jp] = ffma2(ai, bb[jp], acc2[i][jp]);
            }
        }
        __syncthreads();
    }

    // Epilogue: scatter into (b,h,s,d).
    const int n = n0 + tx * 8;
    const int h = n >> 6;
    const int d = n & 63;
    float4 bv0 = *(const float4*)&bias[n];
    float4 bv1 = *(const float4*)&bias[n + 4];
    #pragma unroll
    for (int i = 0; i < 8; i++) {
        int m = m0 + ty * 8 + i;
        int b = m >> 11;
        int s = m & (SEQ - 1);
        float* o = &outp[(((size_t)(b * NHEAD + h)) * SEQ + s) * DHEAD + d];
        float2 p0 = unpk2(acc2[i][0]);
        float2 p1 = unpk2(acc2[i][1]);
        float2 p2 = unpk2(acc2[i][2]);
        float2 p3 = unpk2(acc2[i][3]);
        float4 r0, r1;
        r0.x = p0.x + bv0.x; r0.y = p0.y + bv0.y;
        r0.z = p1.x + bv0.z; r0.w = p1.y + bv0.w;
        r1.x = p2.x + bv1.x; r1.y = p2.y + bv1.y;
        r1.z = p3.x + bv1.z; r1.w = p3.y + bv1.w;
        *(float4*)&o[0] = r0;
        *(float4*)&o[4] = r1;
    }
}

// ---------------------------------------------------------------------------
// Relative-position causal flash attention; FFMA2 inner loops.
// QK/REL: accumulator pairs over (even d, odd d) partial sums, merged before
// softmax. PV: pairs over adjacent output columns, p broadcast-packed.
// SMEM pad 68 floats/row -> conflict-free 128-bit LDS (stride 68%32=4).
// ---------------------------------------------------------------------------
#define AM 128
#define AN 128
#define AP 68
#define PP 132

__global__ __launch_bounds__(256, 1) void relattn_kernel(
    const float* __restrict__ Er, float* __restrict__ out)
{
    extern __shared__ float sm[];
    float* q_s = sm;                    // 128*68 = 8704 floats
    float* k_s = sm + 8704;
    float* v_s = sm + 17408;
    float* ep  = sm + 26112;            // band 256*68=17408 / p 128*132=16896

    const int sb = (int)gridDim.x - 1 - (int)blockIdx.x;  // heavy blocks first
    const int bh = blockIdx.y;
    const int b  = bh >> 4;
    const int h  = bh & 15;
    const int s0 = sb * AM;

    const float* Q = g_q + (size_t)bh * SEQ * DHEAD;
    const float* K = g_k + (size_t)bh * SEQ * DHEAD;
    const float* V = g_v + (size_t)bh * SEQ * DHEAD;

    const int tid = threadIdx.x;
    const int tx = tid & 15;
    const int ty = tid >> 4;

    // Load q tile into padded layout
    {
        const float4* Q4 = (const float4*)(Q + (size_t)s0 * DHEAD);
        #pragma unroll
        for (int u = 0; u < 8; u++) {
            int f = tid + u * 256;
            int row = f >> 4;
            int c4  = f & 15;
            *(float4*)&q_s[row * AP + c4 * 4] = Q4[row * 16 + c4];
        }
    }

    float m_r[8], l_r[8];
    u64 o2[8][2];
    #pragma unroll
    for (int i = 0; i < 8; i++) {
        m_r[i] = -1e30f;
        l_r[i] = 0.f;
        o2[i][0] = 0ull;
        o2[i][1] = 0ull;
    }

    const float4* Er4 = (const float4*)Er;

    for (int t0 = 0; t0 <= s0; t0 += AN) {
        __syncthreads();   // prior p/v reads done before overwrite

        // k, v tiles
        {
            const float4* K4 = (const float4*)(K + (size_t)t0 * DHEAD);
            const float4* V4 = (const float4*)(V + (size_t)t0 * DHEAD);
            #pragma unroll
            for (int u = 0; u < 8; u++) {
                int f = tid + u * 256;
                int row = f >> 4;
                int c4  = f & 15;
                *(float4*)&k_s[row * AP + c4 * 4] = K4[row * 16 + c4];
                *(float4*)&v_s[row * AP + c4 * 4] = V4[row * 16 + c4];
            }
        }
        // Er band rows l0..l0+255; band row r <-> (t-s)-(t0-s0)+127
        {
            int l0 = t0 - s0 + (SEQ - 1) - 127;   // >= 0 always here
            #pragma unroll
            for (int u = 0; u < 16; u++) {
                int f = tid + u * 256;
                int r = f >> 4;
                int gl = l0 + r;
                gl = gl > SEQ - 1 ? SEQ - 1 : gl;   // clamp (masked rows only)
                *(float4*)&ep[r * AP + (f & 15) * 4] = Er4[gl * 16 + (f & 15)];
            }
        }
        __syncthreads();

        // acc2[i][j] = (sum over even d, sum over odd d) of q.k + q.er
        u64 acc2[8][8];
        #pragma unroll
        for (int i = 0; i < 8; i++)
            #pragma unroll
            for (int j = 0; j < 8; j++) acc2[i][j] = 0ull;

        const int bandrow0 = (tx - ty + 15) * AP;   // c=0 (j-i=-7)
        #pragma unroll 1
        for (int d4 = 0; d4 < 16; d4++) {
            ulonglong2 qv[8];
            #pragma unroll
            for (int i = 0; i < 8; i++)
                qv[i] = *(ulonglong2*)&q_s[(ty + 16 * i) * AP + d4 * 4];
            // ---- QK ----
            #pragma unroll
            for (int j = 0; j < 8; j++) {
                ulonglong2 kv = *(ulonglong2*)&k_s[(tx + 16 * j) * AP + d4 * 4];
                #pragma unroll
                for (int i = 0; i < 8; i++)
                    acc2[i][j] = ffma2(qv[i].x, kv.x, acc2[i][j]);
                #pragma unroll
                for (int i = 0; i < 8; i++)
                    acc2[i][j] = ffma2(qv[i].y, kv.y, acc2[i][j]);
            }
            // ---- REL: acc2[i][j] += q_i * band[tx-ty+16(j-i)+127] ----
            #pragma unroll
            for (int c = 0; c < 15; c++) {
                ulonglong2 ev = *(ulonglong2*)&ep[bandrow0 + c * (16 * AP) + d4 * 4];
                #pragma unroll
                for (int i = 0; i < 8; i++) {
                    int j = i + c - 7;
                    if (j >= 0 && j < 8) {
                        acc2[i][j] = ffma2(qv[i].x, ev.x, acc2[i][j]);
                        acc2[i][j] = ffma2(qv[i].y, ev.y, acc2[i][j]);
                    }
                }
            }
        }

        // ---- merge halves + mask + scale + row max ----
        const bool diag = (t0 == s0);
        float accf[8][8];
        float pmax[8];
        #pragma unroll
        for (int i = 0; i < 8; i++) {
            int sgl = ty + 16 * i;
            float mx = -1e30f;
            #pragma unroll
            for (int j = 0; j < 8; j++) {
                int tgl = tx + 16 * j;
                float v = hsum2(acc2[i][j]) * 0.125f;
                if (diag && tgl > sgl) v = -1e30f;
                accf[i][j] = v;
                mx = fmaxf(mx, v);
            }
            #pragma unroll
            for (int off = 8; off > 0; off >>= 1)
                mx = fmaxf(mx, __shfl_xor_sync(0xffffffffu, mx, off));
            pmax[i] = mx;
        }

        __syncthreads();   // band reads done before p overwrites ep

        // ---- online softmax update; write p (conflict-free scalar STS) ----
        #pragma unroll
        for (int i = 0; i < 8; i++) {
            float m_new = fmaxf(m_r[i], pmax[i]);
            float alpha = __expf(m_r[i] - m_new);
            float lsum = 0.f;
            int rowoff = (ty + 16 * i) * PP + tx;
            #pragma unroll
            for (int j = 0; j < 8; j++) {
                float p = __expf(accf[i][j] - m_new);
                ep[rowoff + 16 * j] = p;
                lsum += p;
            }
            #pragma unroll
            for (int off = 8; off > 0; off >>= 1)
                lsum += __shfl_xor_sync(0xffffffffu, lsum, off);
            l_r[i] = l_r[i] * alpha + lsum;
            m_r[i] = m_new;
            u64 al2 = pack2(alpha);
            o2[i][0] = fmul2(o2[i][0], al2);
            o2[i][1] = fmul2(o2[i][1], al2);
        }

        __syncthreads();

        // ---- PV: o2[i] += p[i][t] * v[t][4tx..4tx+3] (c-paired) ----
        #pragma unroll 2
        for (int j4 = 0; j4 < 32; j4++) {
            ulonglong2 vv[4];
            #pragma unroll
            for (int jj = 0; jj < 4; jj++)
                vv[jj] = *(ulonglong2*)&v_s[(j4 * 4 + jj) * AP + tx * 4];
            #pragma unroll
            for (int i = 0; i < 8; i++) {
                float4 pv = *(float4*)&ep[(ty + 16 * i) * PP + j4 * 4];
                u64 p0 = pack2(pv.x);
                o2[i][0] = ffma2(p0, vv[0].x, o2[i][0]);
                o2[i][1] = ffma2(p0, vv[0].y, o2[i][1]);
                u64 p1 = pack2(pv.y);
                o2[i][0] = ffma2(p1, vv[1].x, o2[i][0]);
                o2[i][1] = ffma2(p1, vv[1].y, o2[i][1]);
                u64 p2 = pack2(pv.z);
                o2[i][0] = ffma2(p2, vv[2].x, o2[i][0]);
                o2[i][1] = ffma2(p2, vv[2].y, o2[i][1]);
                u64 p3 = pack2(pv.w);
                o2[i][0] = ffma2(p3, vv[3].x, o2[i][0]);
                o2[i][1] = ffma2(p3, vv[3].y, o2[i][1]);
            }
        }
    }

    // ---- epilogue: out[b][s][h*64 + d] = o / l ----
    #pragma unroll
    for (int i = 0; i < 8; i++) {
        int sg = s0 + ty + 16 * i;
        float inv = 1.f / l_r[i];
        float2 a01 = unpk2(o2[i][0]);
        float2 a23 = unpk2(o2[i][1]);
        float4 r;
        r.x = a01.x * inv;
        r.y = a01.y * inv;
        r.z = a23.x * inv;
        r.w = a23.y * inv;
        *(float4*)&out[((size_t)b * SEQ + sg) * DMODEL + h * DHEAD + tx * 4] = r;
    }
}

// ---------------------------------------------------------------------------
extern "C" void kernel_launch(void* const* d_in, const int* in_sizes, int n_in,
                              void* d_out, int out_size)
{
    const float* x  = (const float*)d_in[0];
    const float* Wq = (const float*)d_in[1];
    const float* bq = (const float*)d_in[2];
    const float* Wk = (const float*)d_in[3];
    const float* bk = (const float*)d_in[4];
    const float* Wv = (const float*)d_in[5];
    const float* bv = (const float*)d_in[6];
    const float* Er = (const float*)d_in[7];
    float* out = (float*)d_out;

    (void)in_sizes; (void)n_in; (void)out_size;

    const int smem_bytes = 43520 * 4;   // 174080
    cudaFuncSetAttribute(relattn_kernel,
                         cudaFuncAttributeMaxDynamicSharedMemorySize, smem_bytes);

    dim3 g1(DMODEL / GN, (BATCH * SEQ) / GM, 3);
    qkv_gemm_kernel<<<g1, 256>>>(x, Wq, bq, Wk, bk, Wv, bv);

    dim3 g2(SEQ / AM, BATCH * NHEAD);
    relattn_kernel<<<g2, 256, smem_bytes>>>(Er, out);
}

// round 5
// speedup vs baseline: 1.1775x; 1.1775x over previous
#include <cuda_runtime.h>
#include <cuda_bf16.h>
#include <cstdint>

// Problem constants
#define BATCH 2
#define SEQ   2048
#define DMODEL 1024
#define NHEAD 16
#define DHEAD 64

__device__ __forceinline__ float to_tf32(float a) {
    float r;
    asm("cvt.rna.tf32.f32 %0, %1;" : "=f"(r) : "f"(a));
    return r;
}

// m16n8k8 tf32 mma. A-fragment SMEM cell order is {a0,a2,a1,a3}, so the
// operand order here is {x, z, y, w} of the loaded uint4.
__device__ __forceinline__ void mma_tf32(float* c, uint4 a, uint32_t b0_, uint32_t b1_) {
    asm volatile(
        "mma.sync.aligned.m16n8k8.row.col.f32.tf32.tf32.f32 "
        "{%0,%1,%2,%3}, {%4,%5,%6,%7}, {%8,%9}, {%0,%1,%2,%3};"
        : "+f"(c[0]), "+f"(c[1]), "+f"(c[2]), "+f"(c[3])
        : "r"(a.x), "r"(a.z), "r"(a.y), "r"(a.w), "r"(b0_), "r"(b1_));
}

// ===========================================================================
// Scratch
// ===========================================================================
__device__ float g_q[BATCH * NHEAD * SEQ * DHEAD];
__device__ float g_k[BATCH * NHEAD * SEQ * DHEAD];
__device__ float g_v[BATCH * NHEAD * SEQ * DHEAD];
__device__ float g_xt[BATCH * SEQ * DMODEL];            // x rounded to tf32
__device__ float g_wt[3 * DMODEL * DMODEL];             // W^T rounded to tf32

// ===========================================================================
// Prep kernels
// ===========================================================================
__global__ __launch_bounds__(256) void prep_x_kernel(const float* __restrict__ x)
{
    int i = blockIdx.x * 256 + threadIdx.x;
    const float4* x4 = (const float4*)x;
    float4 v = x4[i];
    v.x = to_tf32(v.x); v.y = to_tf32(v.y);
    v.z = to_tf32(v.z); v.w = to_tf32(v.w);
    ((float4*)g_xt)[i] = v;
}

__global__ __launch_bounds__(256) void prep_w_kernel(
    const float* __restrict__ W0, const float* __restrict__ W1,
    const float* __restrict__ W2)
{
    __shared__ float t[32][33];
    const int z = blockIdx.z;
    const float* W = (z == 0) ? W0 : (z == 1) ? W1 : W2;
    float* WT = g_wt + (size_t)z * DMODEL * DMODEL;
    const int n0 = blockIdx.x * 32;
    const int k0 = blockIdx.y * 32;
    const int tx = threadIdx.x & 31;
    const int ty = threadIdx.x >> 5;
    #pragma unroll
    for (int r = 0; r < 4; r++)
        t[ty + 8 * r][tx] = to_tf32(W[(size_t)(k0 + ty + 8 * r) * DMODEL + n0 + tx]);
    __syncthreads();
    #pragma unroll
    for (int r = 0; r < 4; r++)
        WT[(size_t)(n0 + ty + 8 * r) * DMODEL + k0 + tx] = t[tx][ty + 8 * r];
}

// ===========================================================================
// QKV GEMM via mma.sync tf32 (m16n8k8). CTA tile 128x128, k-stage 32,
// double-buffered. 8 warps: warp_m = wid>>1 (32 m-rows), warp_n = wid&1
// (64 n-cols). Fragment-packed SMEM:
//   A cell (16B) for (block b = kc*8+mt, lane g*4+t) = {a0,a2,a1,a3}
//     = A[g][t], A[g][t+4], A[g+8][t], A[g+8][t+4]   (element = 2*mrow+khalf)
//   B cell = {b0,b1,b0',b1'} for n-tiles 2*nt2, 2*nt2+1 (element = 2*ntlo+khalf)
// Fragment loads: lane-consecutive 16B cells -> conflict-free LDS.128.
// ===========================================================================
#define TKT 32
#define NKT (DMODEL / TKT)     // 32
#define STAGEF 8192            // floats per stage (A 4096 + B 4096)

__global__ __launch_bounds__(256) void qkv_gemm_mma_kernel(
    const float* __restrict__ b0v, const float* __restrict__ b1v,
    const float* __restrict__ b2v)
{
    extern __shared__ float smf[];   // 2 stages x 8192 floats = 64KB

    const int z  = blockIdx.z;
    const int m0 = blockIdx.y * 128;
    const int n0 = blockIdx.x * 128;
    const float* bias = (z == 0) ? b0v : (z == 1) ? b1v : b2v;
    float* outp       = (z == 0) ? g_q : (z == 1) ? g_k : g_v;
    const float* WT   = g_wt + (size_t)z * DMODEL * DMODEL;
    const float* Xp   = g_xt;

    const int tid = threadIdx.x;
    const int wid = tid >> 5;
    const int lid = tid & 31;
    const int warp_m = wid >> 1;     // 0..3
    const int warp_n = wid & 1;      // 0..1
    const int g = lid >> 2;
    const int t = lid & 3;

    float acc[2][8][4];
    #pragma unroll
    for (int a = 0; a < 2; a++)
        #pragma unroll
        for (int n = 0; n < 8; n++)
            #pragma unroll
            for (int c = 0; c < 4; c++) acc[a][n][c] = 0.f;

    // staging decode for this thread: two (kc, r) items
    int s_kc[2], s_r[2];
    #pragma unroll
    for (int u = 0; u < 2; u++) {
        int f = tid + u * 256;
        s_kc[u] = f >> 7;
        s_r[u]  = f & 127;
    }
    // SMEM store bases (word offsets within a stage)
    int s_offA[2], s_offB[2];
    #pragma unroll
    for (int u = 0; u < 2; u++) {
        int r = s_r[u], kc = s_kc[u];
        s_offA[u] = (kc * 8 + (r >> 4)) * 128 + (r & 7) * 16 + ((r >> 3) & 1) * 2;
        s_offB[u] = 4096 + s_offA[u] - ((r >> 3) & 1) * 2 + ((r >> 3) & 1) * 2; // same formula
    }

    // ---- prologue: stage tile 0 into buffer 0 ----
    #pragma unroll
    for (int u = 0; u < 2; u++) {
        int r = s_r[u], kc = s_kc[u];
        const float4* pA = (const float4*)&Xp[(size_t)(m0 + r) * DMODEL + kc * 8];
        float4 a0 = pA[0], a1 = pA[1];
        float* dA = smf + s_offA[u];
        *(float2*)&dA[0]  = make_float2(a0.x, a1.x);
        *(float2*)&dA[4]  = make_float2(a0.y, a1.y);
        *(float2*)&dA[8]  = make_float2(a0.z, a1.z);
        *(float2*)&dA[12] = make_float2(a0.w, a1.w);
        const float4* pB = (const float4*)&WT[(size_t)(n0 + r) * DMODEL + kc * 8];
        float4 c0 = pB[0], c1 = pB[1];
        float* dB = smf + s_offB[u];
        *(float2*)&dB[0]  = make_float2(c0.x, c1.x);
        *(float2*)&dB[4]  = make_float2(c0.y, c1.y);
        *(float2*)&dB[8]  = make_float2(c0.z, c1.z);
        *(float2*)&dB[12] = make_float2(c0.w, c1.w);
    }
    __syncthreads();

    for (int ktile = 0; ktile < NKT; ktile++) {
        const int buf = ktile & 1;

        // prefetch next tile to regs
        float4 ra[4], rb[4];
        if (ktile + 1 < NKT) {
            const int kt = (ktile + 1) * TKT;
            #pragma unroll
            for (int u = 0; u < 2; u++) {
                int r = s_r[u], kc = s_kc[u];
                const float4* pA = (const float4*)&Xp[(size_t)(m0 + r) * DMODEL + kt + kc * 8];
                ra[2 * u]     = pA[0];
                ra[2 * u + 1] = pA[1];
                const float4* pB = (const float4*)&WT[(size_t)(n0 + r) * DMODEL + kt + kc * 8];
                rb[2 * u]     = pB[0];
                rb[2 * u + 1] = pB[1];
            }
        }

        // compute from current buffer
        const float* Ap = smf + buf * STAGEF;
        const float* Bp = Ap + 4096;
        #pragma unroll
        for (int kc = 0; kc < 4; kc++) {
            uint4 af[2];
            af[0] = *(const uint4*)&Ap[kc * 1024 + (warp_m * 2 + 0) * 128 + lid * 4];
            af[1] = *(const uint4*)&Ap[kc * 1024 + (warp_m * 2 + 1) * 128 + lid * 4];
            #pragma unroll
            for (int bp = 0; bp < 4; bp++) {
                uint4 bf = *(const uint4*)&Bp[kc * 1024 + (warp_n * 4 + bp) * 128 + lid * 4];
                #pragma unroll
                for (int amt = 0; amt < 2; amt++) {
                    mma_tf32(acc[amt][2 * bp],     af[amt], bf.x, bf.y);
                    mma_tf32(acc[amt][2 * bp + 1], af[amt], bf.z, bf.w);
                }
            }
        }

        // store prefetched tile into other buffer
        if (ktile + 1 < NKT) {
            float* dst = smf + (buf ^ 1) * STAGEF;
            #pragma unroll
            for (int u = 0; u < 2; u++) {
                float4 a0 = ra[2 * u], a1 = ra[2 * u + 1];
                float* dA = dst + s_offA[u];
                *(float2*)&dA[0]  = make_float2(a0.x, a1.x);
                *(float2*)&dA[4]  = make_float2(a0.y, a1.y);
                *(float2*)&dA[8]  = make_float2(a0.z, a1.z);
                *(float2*)&dA[12] = make_float2(a0.w, a1.w);
                float4 c0 = rb[2 * u], c1 = rb[2 * u + 1];
                float* dB = dst + s_offB[u];
                *(float2*)&dB[0]  = make_float2(c0.x, c1.x);
                *(float2*)&dB[4]  = make_float2(c0.y, c1.y);
                *(float2*)&dB[8]  = make_float2(c0.z, c1.z);
                *(float2*)&dB[12] = make_float2(c0.w, c1.w);
            }
        }
        __syncthreads();
    }

    // ---- epilogue: bias + scatter to (b,h,s,d) ----
    #pragma unroll
    for (int amt = 0; amt < 2; amt++) {
        const int mA = m0 + warp_m * 32 + amt * 16 + g;
        const int bA = mA >> 11;
        const int sA = mA & (SEQ - 1);
        const int mB = mA + 8;
        const int sB = mB & (SEQ - 1);
        #pragma unroll
        for (int nt = 0; nt < 8; nt++) {
            const int n = n0 + warp_n * 64 + nt * 8 + t * 2;
            const int h = n >> 6;
            const int d = n & 63;
            const float2 bb = *(const float2*)&bias[n];
            float* p0 = &outp[(((size_t)(bA * NHEAD + h)) * SEQ + sA) * DHEAD + d];
            float* p1 = &outp[(((size_t)(bA * NHEAD + h)) * SEQ + sB) * DHEAD + d];
            *(float2*)p0 = make_float2(acc[amt][nt][0] + bb.x, acc[amt][nt][1] + bb.y);
            *(float2*)p1 = make_float2(acc[amt][nt][2] + bb.x, acc[amt][nt][3] + bb.y);
        }
    }
}

// ===========================================================================
// Relative-position causal flash attention (R2 winner, unchanged).
// ===========================================================================
#define AM 128
#define AN 128
#define AP 68
#define PP 132

__global__ __launch_bounds__(256, 1) void relattn_kernel(
    const float* __restrict__ Er, float* __restrict__ out)
{
    extern __shared__ float sm[];
    float* q_s = sm;                    // 128*68 = 8704 floats
    float* k_s = sm + 8704;
    float* v_s = sm + 17408;
    float* ep  = sm + 26112;            // band 256*68=17408 / p 128*132=16896

    const int sb = (int)gridDim.x - 1 - (int)blockIdx.x;  // heavy blocks first
    const int bh = blockIdx.y;
    const int b  = bh >> 4;
    const int h  = bh & 15;
    const int s0 = sb * AM;

    const float* Q = g_q + (size_t)bh * SEQ * DHEAD;
    const float* K = g_k + (size_t)bh * SEQ * DHEAD;
    const float* V = g_v + (size_t)bh * SEQ * DHEAD;

    const int tid = threadIdx.x;
    const int tx = tid & 15;
    const int ty = tid >> 4;

    {
        const float4* Q4 = (const float4*)(Q + (size_t)s0 * DHEAD);
        #pragma unroll
        for (int u = 0; u < 8; u++) {
            int f = tid + u * 256;
            int row = f >> 4;
            int c4  = f & 15;
            *(float4*)&q_s[row * AP + c4 * 4] = Q4[row * 16 + c4];
        }
    }

    float m_r[8], l_r[8];
    float o_acc[8][4];
    #pragma unroll
    for (int i = 0; i < 8; i++) {
        m_r[i] = -1e30f;
        l_r[i] = 0.f;
        #pragma unroll
        for (int c = 0; c < 4; c++) o_acc[i][c] = 0.f;
    }

    const float4* Er4 = (const float4*)Er;

    for (int t0 = 0; t0 <= s0; t0 += AN) {
        __syncthreads();

        {
            const float4* K4 = (const float4*)(K + (size_t)t0 * DHEAD);
            const float4* V4 = (const float4*)(V + (size_t)t0 * DHEAD);
            #pragma unroll
            for (int u = 0; u < 8; u++) {
                int f = tid + u * 256;
                int row = f >> 4;
                int c4  = f & 15;
                *(float4*)&k_s[row * AP + c4 * 4] = K4[row * 16 + c4];
                *(float4*)&v_s[row * AP + c4 * 4] = V4[row * 16 + c4];
            }
        }
        {
            int l0 = t0 - s0 + (SEQ - 1) - 127;
            #pragma unroll
            for (int u = 0; u < 16; u++) {
                int f = tid + u * 256;
                int r = f >> 4;
                int gl = l0 + r;
                gl = gl > SEQ - 1 ? SEQ - 1 : gl;
                *(float4*)&ep[r * AP + (f & 15) * 4] = Er4[gl * 16 + (f & 15)];
            }
        }
        __syncthreads();

        float acc[8][8];
        #pragma unroll
        for (int i = 0; i < 8; i++)
            #pragma unroll
            for (int j = 0; j < 8; j++) acc[i][j] = 0.f;

        const int bandrow0 = (tx - ty + 15) * AP;
        #pragma unroll 2
        for (int d4 = 0; d4 < 16; d4++) {
            float4 qv[8], kv[8];
            #pragma unroll
            for (int i = 0; i < 8; i++)
                qv[i] = *(float4*)&q_s[(ty + 16 * i) * AP + d4 * 4];
            #pragma unroll
            for (int j = 0; j < 8; j++)
                kv[j] = *(float4*)&k_s[(tx + 16 * j) * AP + d4 * 4];
            #pragma unroll
            for (int i = 0; i < 8; i++)
                #pragma unroll
                for (int j = 0; j < 8; j++)
                    acc[i][j] += qv[i].x * kv[j].x + qv[i].y * kv[j].y +
                                 qv[i].z * kv[j].z + qv[i].w * kv[j].w;
            #pragma unroll
            for (int c = 0; c < 15; c++) {
                float4 ev = *(float4*)&ep[bandrow0 + c * (16 * AP) + d4 * 4];
                #pragma unroll
                for (int i = 0; i < 8; i++) {
                    int j = i + c - 7;
                    if (j >= 0 && j < 8)
                        acc[i][j] += qv[i].x * ev.x + qv[i].y * ev.y +
                                     qv[i].z * ev.z + qv[i].w * ev.w;
                }
            }
        }

        const bool diag = (t0 == s0);
        float pmax[8];
        #pragma unroll
        for (int i = 0; i < 8; i++) {
            int sgl = ty + 16 * i;
            float mx = -1e30f;
            #pragma unroll
            for (int j = 0; j < 8; j++) {
                int tgl = tx + 16 * j;
                float v = acc[i][j] * 0.125f;
                if (diag && tgl > sgl) v = -1e30f;
                acc[i][j] = v;
                mx = fmaxf(mx, v);
            }
            #pragma unroll
            for (int off = 8; off > 0; off >>= 1)
                mx = fmaxf(mx, __shfl_xor_sync(0xffffffffu, mx, off));
            pmax[i] = mx;
        }

        __syncthreads();

        #pragma unroll
        for (int i = 0; i < 8; i++) {
            float m_new = fmaxf(m_r[i], pmax[i]);
            float alpha = __expf(m_r[i] - m_new);
            float lsum = 0.f;
            int rowoff = (ty + 16 * i) * PP + tx;
            #pragma unroll
            for (int j = 0; j < 8; j++) {
                float p = __expf(acc[i][j] - m_new);
                ep[rowoff + 16 * j] = p;
                lsum += p;
            }
            #pragma unroll
            for (int off = 8; off > 0; off >>= 1)
                lsum += __shfl_xor_sync(0xffffffffu, lsum, off);
            l_r[i] = l_r[i] * alpha + lsum;
            m_r[i] = m_new;
            #pragma unroll
            for (int c = 0; c < 4; c++) o_acc[i][c] *= alpha;
        }

        __syncthreads();

        #pragma unroll 4
        for (int j4 = 0; j4 < 32; j4++) {
            float4 vv[4];
            #pragma unroll
            for (int jj = 0; jj < 4; jj++)
                vv[jj] = *(float4*)&v_s[(j4 * 4 + jj) * AP + tx * 4];
            #pragma unroll
            for (int i = 0; i < 8; i++) {
                float4 pv = *(float4*)&ep[(ty + 16 * i) * PP + j4 * 4];
                o_acc[i][0] += pv.x * vv[0].x + pv.y * vv[1].x + pv.z * vv[2].x + pv.w * vv[3].x;
                o_acc[i][1] += pv.x * vv[0].y + pv.y * vv[1].y + pv.z * vv[2].y + pv.w * vv[3].y;
                o_acc[i][2] += pv.x * vv[0].z + pv.y * vv[1].z + pv.z * vv[2].z + pv.w * vv[3].z;
                o_acc[i][3] += pv.x * vv[0].w + pv.y * vv[1].w + pv.z * vv[2].w + pv.w * vv[3].w;
            }
        }
    }

    #pragma unroll
    for (int i = 0; i < 8; i++) {
        int sg = s0 + ty + 16 * i;
        float inv = 1.f / l_r[i];
        float4 r;
        r.x = o_acc[i][0] * inv;
        r.y = o_acc[i][1] * inv;
        r.z = o_acc[i][2] * inv;
        r.w = o_acc[i][3] * inv;
        *(float4*)&out[((size_t)b * SEQ + sg) * DMODEL + h * DHEAD + tx * 4] = r;
    }
}

// ===========================================================================
extern "C" void kernel_launch(void* const* d_in, const int* in_sizes, int n_in,
                              void* d_out, int out_size)
{
    const float* x  = (const float*)d_in[0];
    const float* Wq = (const float*)d_in[1];
    const float* bq = (const float*)d_in[2];
    const float* Wk = (const float*)d_in[3];
    const float* bk = (const float*)d_in[4];
    const float* Wv = (const float*)d_in[5];
    const float* bv = (const float*)d_in[6];
    const float* Er = (const float*)d_in[7];
    float* out = (float*)d_out;

    (void)in_sizes; (void)n_in; (void)out_size;

    const int attn_smem = 43520 * 4;    // 174080
    cudaFuncSetAttribute(relattn_kernel,
                         cudaFuncAttributeMaxDynamicSharedMemorySize, attn_smem);
    const int gemm_smem = 2 * STAGEF * 4;   // 65536
    cudaFuncSetAttribute(qkv_gemm_mma_kernel,
                         cudaFuncAttributeMaxDynamicSharedMemorySize, gemm_smem);

    prep_x_kernel<<<(BATCH * SEQ * DMODEL) / (4 * 256), 256>>>(x);
    prep_w_kernel<<<dim3(DMODEL / 32, DMODEL / 32, 3), 256>>>(Wq, Wk, Wv);

    dim3 gg(DMODEL / 128, (BATCH * SEQ) / 128, 3);
    qkv_gemm_mma_kernel<<<gg, 256, gemm_smem>>>(bq, bk, bv);

    dim3 g2(SEQ / AM, BATCH * NHEAD);
    relattn_kernel<<<g2, 256, attn_smem>>>(Er, out);
}